// round 16
// baseline (speedup 1.0000x reference)
#include <cuda_runtime.h>
#include <cuda_fp16.h>
#include <mma.h>
#include <math.h>
#include <stdint.h>

using namespace nvcuda;

#define NN 50000
#define HH 4
#define CC 32
#define F1 128
#define F2 64
#define NEG 0.2f
#define EPSV 1e-16f
#define EMAX 1600000   // real edges only (self loops handled analytically)
#define NBLK ((NN + 255) / 256)
#define NPAD 50048     // NN rounded up to multiple of 64 (wmma tile safety)

// ---------------- scratch (device globals; no allocations allowed) ----------
__device__ __align__(16) __half g_xw1h[NN * F1];   // x@W1 half (agg1 gather)
__device__ __align__(16) __half g_h1h[NPAD * F1];  // layer1 output, half (gemm2 A)
__device__ float  g_asrc1[NN * HH];
__device__ float  g_adst1[NN * HH];
__device__ __align__(16) __half g_xw2h[NN * F2];   // h@W2 half (agg2 gather)
__device__ __align__(16) __half g_w2h[F1 * F2];    // W2 converted to half
__device__ float  g_asrc2[NN];
__device__ float  g_adst2[NN];
__device__ int    g_deg[NN];          // ZERO before each use; scanA re-zeroes
__device__ int    g_off[NN];          // CSR segment start
__device__ int    g_cur[NN];          // scatter cursor
__device__ int    g_bsum[256];        // block sums for scan
__device__ int    g_csr[EMAX];        // src node per edge, grouped by dst

// ---------------- GEMM1: xw1h = half(x @ W1), fused attn1 -------------------
__global__ __launch_bounds__(256) void gemm1_kernel(
    const float* __restrict__ A, const float* __restrict__ B,
    __half* __restrict__ Ch,
    const float* __restrict__ att_src, const float* __restrict__ att_dst, int M)
{
    const int BM = 128, BN = 128, BK = 8, KTOT = 128, NT = 256, TX = 16;
    __shared__ float As[2][BK * BM];
    __shared__ float Bs[2][BK * BN];

    int tid = threadIdx.x;
    int tx = tid % TX;
    int ty = tid / TX;
    int row0 = blockIdx.y * BM;

    float acc[8][8] = {};

    auto load_tile = [&](int buf, int kt) {
        int k0 = kt * BK;
        #pragma unroll
        for (int idx = tid; idx < BM * BK / 4; idx += NT) {
            int row = idx >> 1;
            int kc  = (idx & 1) * 4;
            int gr = row0 + row;
            float4 v = make_float4(0.f, 0.f, 0.f, 0.f);
            if (gr < M) v = *(const float4*)(A + (size_t)gr * KTOT + k0 + kc);
            As[buf][(kc + 0) * BM + row] = v.x;
            As[buf][(kc + 1) * BM + row] = v.y;
            As[buf][(kc + 2) * BM + row] = v.z;
            As[buf][(kc + 3) * BM + row] = v.w;
        }
        #pragma unroll
        for (int idx = tid; idx < BK * BN / 4; idx += NT) {
            int r  = idx / (BN / 4);
            int c4 = (idx % (BN / 4)) * 4;
            *(float4*)&Bs[buf][r * BN + c4] =
                *(const float4*)(B + (size_t)(k0 + r) * BN + c4);
        }
    };

    load_tile(0, 0);
    __syncthreads();

    int buf = 0;
    for (int kt = 0; kt < KTOT / BK; kt++) {
        if (kt + 1 < KTOT / BK) load_tile(buf ^ 1, kt + 1);
        #pragma unroll
        for (int kk = 0; kk < BK; kk++) {
            float4 a0 = *(const float4*)&As[buf][kk * BM + ty * 8];
            float4 a1 = *(const float4*)&As[buf][kk * BM + ty * 8 + 4];
            float4 b0 = *(const float4*)&Bs[buf][kk * BN + tx * 8];
            float4 b1 = *(const float4*)&Bs[buf][kk * BN + tx * 8 + 4];
            float av[8] = {a0.x,a0.y,a0.z,a0.w,a1.x,a1.y,a1.z,a1.w};
            float bv[8] = {b0.x,b0.y,b0.z,b0.w,b1.x,b1.y,b1.z,b1.w};
            #pragma unroll
            for (int i = 0; i < 8; i++)
                #pragma unroll
                for (int j = 0; j < 8; j++)
                    acc[i][j] = fmaf(av[i], bv[j], acc[i][j]);
        }
        __syncthreads();
        buf ^= 1;
    }

    float as1[8], ad1[8];
    #pragma unroll
    for (int j = 0; j < 8; j++) {
        as1[j] = att_src[tx * 8 + j];
        ad1[j] = att_dst[tx * 8 + j];
    }
    int h = tx >> 2;

    #pragma unroll
    for (int i = 0; i < 8; i++) {
        int gr = row0 + ty * 8 + i;
        float ps = 0.f, pd = 0.f;
        #pragma unroll
        for (int j = 0; j < 8; j++) {
            ps = fmaf(acc[i][j], as1[j], ps);
            pd = fmaf(acc[i][j], ad1[j], pd);
        }
        ps += __shfl_xor_sync(0xffffffffu, ps, 1);
        pd += __shfl_xor_sync(0xffffffffu, pd, 1);
        ps += __shfl_xor_sync(0xffffffffu, ps, 2);
        pd += __shfl_xor_sync(0xffffffffu, pd, 2);
        if (gr < M) {
            __half2 p0 = __floats2half2_rn(acc[i][0], acc[i][1]);
            __half2 p1 = __floats2half2_rn(acc[i][2], acc[i][3]);
            __half2 p2 = __floats2half2_rn(acc[i][4], acc[i][5]);
            __half2 p3 = __floats2half2_rn(acc[i][6], acc[i][7]);
            uint4 u = make_uint4(*(unsigned*)&p0, *(unsigned*)&p1,
                                 *(unsigned*)&p2, *(unsigned*)&p3);
            *(uint4*)(Ch + (size_t)gr * BN + tx * 8) = u;
            if ((tx & 3) == 0) {
                g_asrc1[gr * 4 + h] = ps;
                g_adst1[gr * 4 + h] = pd;
            }
        }
    }
}

// ---------------- W2 fp32 -> fp16 conversion --------------------------------
__global__ __launch_bounds__(256) void w2conv_kernel(const float* __restrict__ W2) {
    int i = blockIdx.x * blockDim.x + threadIdx.x;
    if (i < F1 * F2) g_w2h[i] = __float2half_rn(W2[i]);
}

// ---------------- GEMM2 (HMMA): xw2h = half(h1h @ W2h), fused attn2 ---------
__global__ __launch_bounds__(128) void gemm2_wmma(
    const __half* __restrict__ A,      // g_h1h [NPAD,128]
    __half* __restrict__ Ch,           // g_xw2h [NN,64]
    const float* __restrict__ att_src, const float* __restrict__ att_dst, int M)
{
    __shared__ float sm[64 * 64];
    int tid  = threadIdx.x;
    int warp = tid >> 5;
    int blk0 = blockIdx.x * 64;
    int row0 = blk0 + warp * 16;

    wmma::fragment<wmma::accumulator, 16, 16, 16, float> acc[4];
    #pragma unroll
    for (int n = 0; n < 4; n++) wmma::fill_fragment(acc[n], 0.f);

    wmma::fragment<wmma::matrix_a, 16, 16, 16, __half, wmma::row_major> afrag;
    wmma::fragment<wmma::matrix_b, 16, 16, 16, __half, wmma::row_major> bfrag;

    #pragma unroll
    for (int k0 = 0; k0 < F1; k0 += 16) {
        wmma::load_matrix_sync(afrag, A + (size_t)row0 * F1 + k0, F1);
        #pragma unroll
        for (int n = 0; n < 4; n++) {
            wmma::load_matrix_sync(bfrag, g_w2h + (size_t)k0 * F2 + n * 16, F2);
            wmma::mma_sync(acc[n], afrag, bfrag, acc[n]);
        }
    }

    #pragma unroll
    for (int n = 0; n < 4; n++)
        wmma::store_matrix_sync(&sm[warp * 16 * 64 + n * 16], acc[n], 64,
                                wmma::mem_row_major);
    __syncthreads();

    int r    = tid >> 1;
    int halfi = tid & 1;
    int gr = blk0 + r;
    const float* rowp = &sm[r * 64 + halfi * 32];
    const float* asp = att_src + halfi * 32;
    const float* adp = att_dst + halfi * 32;

    float ps = 0.f, pd = 0.f;
    float v[32];
    #pragma unroll
    for (int j = 0; j < 32; j++) {
        v[j] = rowp[j];
        ps = fmaf(v[j], asp[j], ps);
        pd = fmaf(v[j], adp[j], pd);
    }
    ps += __shfl_xor_sync(0xffffffffu, ps, 1);
    pd += __shfl_xor_sync(0xffffffffu, pd, 1);

    if (gr < M) {
        #pragma unroll
        for (int c = 0; c < 4; c++) {
            __half2 p0 = __floats2half2_rn(v[c*8+0], v[c*8+1]);
            __half2 p1 = __floats2half2_rn(v[c*8+2], v[c*8+3]);
            __half2 p2 = __floats2half2_rn(v[c*8+4], v[c*8+5]);
            __half2 p3 = __floats2half2_rn(v[c*8+6], v[c*8+7]);
            uint4 u = make_uint4(*(unsigned*)&p0, *(unsigned*)&p1,
                                 *(unsigned*)&p2, *(unsigned*)&p3);
            *(uint4*)(Ch + (size_t)gr * F2 + halfi * 32 + c * 8) = u;
        }
        if (halfi == 0) {
            g_asrc2[gr] = ps;
            g_adst2[gr] = pd;
        }
    }
}

// ---------------- CSR build (real edges only) -------------------------------
__global__ __launch_bounds__(256) void hist8_kernel(const int* __restrict__ dstp, int E) {
    int i = blockIdx.x * blockDim.x + threadIdx.x;
    int e8 = i * 8;
    if (e8 + 7 < E) {
        int4 a = *(const int4*)(dstp + e8);
        int4 b = *(const int4*)(dstp + e8 + 4);
        atomicAdd(&g_deg[a.x], 1); atomicAdd(&g_deg[a.y], 1);
        atomicAdd(&g_deg[a.z], 1); atomicAdd(&g_deg[a.w], 1);
        atomicAdd(&g_deg[b.x], 1); atomicAdd(&g_deg[b.y], 1);
        atomicAdd(&g_deg[b.z], 1); atomicAdd(&g_deg[b.w], 1);
    } else {
        for (int e = e8; e < E; e++) atomicAdd(&g_deg[dstp[e]], 1);
    }
}

__global__ __launch_bounds__(256) void hist1_kernel(const int* __restrict__ dstp, int E) {
    int e = blockIdx.x * blockDim.x + threadIdx.x;
    if (e < E) atomicAdd(&g_deg[dstp[e]], 1);
}

__global__ __launch_bounds__(256) void scanA_kernel() {
    __shared__ int wsum[8];
    int t = threadIdx.x, lane = t & 31, w = t >> 5;
    int idx = blockIdx.x * 256 + t;
    int v = (idx < NN) ? g_deg[idx] : 0;
    int x = v;
    #pragma unroll
    for (int o = 1; o < 32; o <<= 1) {
        int tt = __shfl_up_sync(0xffffffffu, x, o);
        if (lane >= o) x += tt;
    }
    if (lane == 31) wsum[w] = x;
    __syncthreads();
    if (w == 0) {
        int s = (lane < 8) ? wsum[lane] : 0;
        #pragma unroll
        for (int o = 1; o < 8; o <<= 1) {
            int tt = __shfl_up_sync(0xffffffffu, s, o);
            if (lane >= o) s += tt;
        }
        if (lane < 8) wsum[lane] = s;
    }
    __syncthreads();
    int pre = (w > 0 ? wsum[w - 1] : 0) + (x - v);
    if (idx < NN) {
        g_off[idx] = pre;
        g_deg[idx] = 0;               // self-clean for next invocation
    }
    if (t == 255) g_bsum[blockIdx.x] = pre + v;
}

__global__ __launch_bounds__(256) void scanC_kernel() {
    __shared__ int wsum[8];
    __shared__ int s_total;
    int t = threadIdx.x, lane = t & 31, w = t >> 5;
    int v = (t < (int)blockIdx.x && t < NBLK) ? g_bsum[t] : 0;
    #pragma unroll
    for (int o = 16; o > 0; o >>= 1) v += __shfl_xor_sync(0xffffffffu, v, o);
    if (lane == 0) wsum[w] = v;
    __syncthreads();
    if (t == 0) {
        int s = 0;
        #pragma unroll
        for (int k = 0; k < 8; k++) s += wsum[k];
        s_total = s;
    }
    __syncthreads();
    int idx = blockIdx.x * 256 + t;
    if (idx < NN) {
        int o = g_off[idx] + s_total;
        g_off[idx] = o;
        g_cur[idx] = o;
    }
}

__global__ __launch_bounds__(256) void scatter8_kernel(
    const int* __restrict__ srcp, const int* __restrict__ dstp, int E)
{
    int i = blockIdx.x * blockDim.x + threadIdx.x;
    int e8 = i * 8;
    if (e8 + 7 < E) {
        int4 sa = *(const int4*)(srcp + e8);
        int4 sb = *(const int4*)(srcp + e8 + 4);
        int4 da = *(const int4*)(dstp + e8);
        int4 db = *(const int4*)(dstp + e8 + 4);
        g_csr[atomicAdd(&g_cur[da.x], 1)] = sa.x;
        g_csr[atomicAdd(&g_cur[da.y], 1)] = sa.y;
        g_csr[atomicAdd(&g_cur[da.z], 1)] = sa.z;
        g_csr[atomicAdd(&g_cur[da.w], 1)] = sa.w;
        g_csr[atomicAdd(&g_cur[db.x], 1)] = sb.x;
        g_csr[atomicAdd(&g_cur[db.y], 1)] = sb.y;
        g_csr[atomicAdd(&g_cur[db.z], 1)] = sb.z;
        g_csr[atomicAdd(&g_cur[db.w], 1)] = sb.w;
    } else {
        for (int e = e8; e < E; e++)
            g_csr[atomicAdd(&g_cur[dstp[e]], 1)] = srcp[e];
    }
}

__global__ __launch_bounds__(256) void scatter1_kernel(
    const int* __restrict__ srcp, const int* __restrict__ dstp, int E)
{
    int e = blockIdx.x * blockDim.x + threadIdx.x;
    if (e < E) g_csr[atomicAdd(&g_cur[dstp[e]], 1)] = srcp[e];
}

// ---------------- layer 1 fused gather: TWO nodes per warp, interleaved -----
// R11/R14 per-node geometry (lane: 8 cols, half-warps 2 edges/step), with two
// independent node states per warp -> 4 gather chains in flight. No smem.
__global__ __launch_bounds__(256) void agg1_kernel(
    const float* __restrict__ b1,
    const float* __restrict__ gamma, const float* __restrict__ beta,
    const float* __restrict__ mean,  const float* __restrict__ var, int E)
{
    int gw = (blockIdx.x * blockDim.x + threadIdx.x) >> 5;
    int lane = threadIdx.x & 31;
    if (gw >= NN / 2) return;
    int d0 = gw * 2, d1 = d0 + 1;

    int sub = lane & 15;
    int hf  = lane >> 4;
    int h = sub >> 2;
    float ad0 = g_adst1[d0 * 4 + h];
    float ad1 = g_adst1[d1 * 4 + h];

    int st0 = g_off[d0];
    int en0 = g_off[d1];
    int st1 = en0;
    int en1 = (d1 + 1 < NN) ? g_off[d1 + 1] : E;

    float acc0[8] = {}, acc1[8] = {};
    float ss0 = 0.f, ss1 = 0.f;

    if (hf == 0) {
        {
            float e0 = g_asrc1[d0 * 4 + h] + ad0;
            float w0 = __expf(e0 > 0.f ? e0 : NEG * e0);
            ss0 = w0;
            uint4 raw = *(const uint4*)(g_xw1h + (size_t)d0 * F1 + sub * 8);
            float2 f0 = __half22float2(*(__half2*)&raw.x);
            float2 f1 = __half22float2(*(__half2*)&raw.y);
            float2 f2 = __half22float2(*(__half2*)&raw.z);
            float2 f3 = __half22float2(*(__half2*)&raw.w);
            acc0[0] = w0*f0.x; acc0[1] = w0*f0.y; acc0[2] = w0*f1.x; acc0[3] = w0*f1.y;
            acc0[4] = w0*f2.x; acc0[5] = w0*f2.y; acc0[6] = w0*f3.x; acc0[7] = w0*f3.y;
        }
        {
            float e0 = g_asrc1[d1 * 4 + h] + ad1;
            float w0 = __expf(e0 > 0.f ? e0 : NEG * e0);
            ss1 = w0;
            uint4 raw = *(const uint4*)(g_xw1h + (size_t)d1 * F1 + sub * 8);
            float2 f0 = __half22float2(*(__half2*)&raw.x);
            float2 f1 = __half22float2(*(__half2*)&raw.y);
            float2 f2 = __half22float2(*(__half2*)&raw.z);
            float2 f3 = __half22float2(*(__half2*)&raw.w);
            acc1[0] = w0*f0.x; acc1[1] = w0*f0.y; acc1[2] = w0*f1.x; acc1[3] = w0*f1.y;
            acc1[4] = w0*f2.x; acc1[5] = w0*f2.y; acc1[6] = w0*f3.x; acc1[7] = w0*f3.y;
        }
    }

    int i0 = st0, i1 = st1;
    while (i0 < en0 || i1 < en1) {
        int c0 = (i0 < en0) ? min(en0 - i0, 32) : 0;
        int c1 = (i1 < en1) ? min(en1 - i1, 32) : 0;
        int sj0 = (lane < c0) ? g_csr[i0 + lane] : 0;
        int sj1 = (lane < c1) ? g_csr[i1 + lane] : 0;
        int cmax = max(c0, c1);
        for (int k = 0; k < cmax; k += 2) {
            int kk = k + hf;
            int selA = kk < c0 ? kk : 0;
            int selB = kk < c1 ? kk : 0;
            int sA = __shfl_sync(0xffffffffu, sj0, selA);
            int sB = __shfl_sync(0xffffffffu, sj1, selB);
            if (kk < c0) {
                float e = g_asrc1[sA * 4 + h] + ad0;
                float w = __expf(e > 0.f ? e : NEG * e);
                uint4 raw = *(const uint4*)(g_xw1h + (size_t)sA * F1 + sub * 8);
                float2 f0 = __half22float2(*(__half2*)&raw.x);
                float2 f1 = __half22float2(*(__half2*)&raw.y);
                float2 f2 = __half22float2(*(__half2*)&raw.z);
                float2 f3 = __half22float2(*(__half2*)&raw.w);
                ss0 += w;
                acc0[0] = fmaf(w, f0.x, acc0[0]); acc0[1] = fmaf(w, f0.y, acc0[1]);
                acc0[2] = fmaf(w, f1.x, acc0[2]); acc0[3] = fmaf(w, f1.y, acc0[3]);
                acc0[4] = fmaf(w, f2.x, acc0[4]); acc0[5] = fmaf(w, f2.y, acc0[5]);
                acc0[6] = fmaf(w, f3.x, acc0[6]); acc0[7] = fmaf(w, f3.y, acc0[7]);
            }
            if (kk < c1) {
                float e = g_asrc1[sB * 4 + h] + ad1;
                float w = __expf(e > 0.f ? e : NEG * e);
                uint4 raw = *(const uint4*)(g_xw1h + (size_t)sB * F1 + sub * 8);
                float2 f0 = __half22float2(*(__half2*)&raw.x);
                float2 f1 = __half22float2(*(__half2*)&raw.y);
                float2 f2 = __half22float2(*(__half2*)&raw.z);
                float2 f3 = __half22float2(*(__half2*)&raw.w);
                ss1 += w;
                acc1[0] = fmaf(w, f0.x, acc1[0]); acc1[1] = fmaf(w, f0.y, acc1[1]);
                acc1[2] = fmaf(w, f1.x, acc1[2]); acc1[3] = fmaf(w, f1.y, acc1[3]);
                acc1[4] = fmaf(w, f2.x, acc1[4]); acc1[5] = fmaf(w, f2.y, acc1[5]);
                acc1[6] = fmaf(w, f3.x, acc1[6]); acc1[7] = fmaf(w, f3.y, acc1[7]);
            }
        }
        i0 += 32; i1 += 32;
    }

    // combine the two half-warps per node
    ss0 += __shfl_xor_sync(0xffffffffu, ss0, 16);
    ss1 += __shfl_xor_sync(0xffffffffu, ss1, 16);
    #pragma unroll
    for (int j = 0; j < 8; j++) {
        acc0[j] += __shfl_xor_sync(0xffffffffu, acc0[j], 16);
        acc1[j] += __shfl_xor_sync(0xffffffffu, acc1[j], 16);
    }

    if (hf == 0) {
        int c0 = sub * 8;
        float inv0 = 1.f / (ss0 + EPSV);
        float inv1 = 1.f / (ss1 + EPSV);
        float o0[8], o1[8];
        #pragma unroll
        for (int j = 0; j < 8; j++) {
            int c = c0 + j;
            float bb = b1[c], mm = mean[c];
            float sc = rsqrtf(var[c] + 1e-5f) * gamma[c];
            float bt = beta[c];
            float h0 = (acc0[j] * inv0 + bb - mm) * sc + bt;
            float h1v = (acc1[j] * inv1 + bb - mm) * sc + bt;
            o0[j] = h0 > 0.f ? h0 : expm1f(h0);
            o1[j] = h1v > 0.f ? h1v : expm1f(h1v);
        }
        {
            __half2 p0 = __floats2half2_rn(o0[0], o0[1]);
            __half2 p1 = __floats2half2_rn(o0[2], o0[3]);
            __half2 p2 = __floats2half2_rn(o0[4], o0[5]);
            __half2 p3 = __floats2half2_rn(o0[6], o0[7]);
            uint4 u = make_uint4(*(unsigned*)&p0, *(unsigned*)&p1,
                                 *(unsigned*)&p2, *(unsigned*)&p3);
            *(uint4*)(g_h1h + (size_t)d0 * F1 + c0) = u;
        }
        {
            __half2 p0 = __floats2half2_rn(o1[0], o1[1]);
            __half2 p1 = __floats2half2_rn(o1[2], o1[3]);
            __half2 p2 = __floats2half2_rn(o1[4], o1[5]);
            __half2 p3 = __floats2half2_rn(o1[6], o1[7]);
            uint4 u = make_uint4(*(unsigned*)&p0, *(unsigned*)&p1,
                                 *(unsigned*)&p2, *(unsigned*)&p3);
            *(uint4*)(g_h1h + (size_t)d1 * F1 + c0) = u;
        }
    }
}

// ---------------- layer 2 fused gather: TWO nodes per warp, interleaved -----
__global__ __launch_bounds__(256) void agg2_kernel(
    float* __restrict__ out, const float* __restrict__ b2, int E)
{
    int gw = (blockIdx.x * blockDim.x + threadIdx.x) >> 5;
    int lane = threadIdx.x & 31;
    if (gw >= NN / 2) return;
    int d0 = gw * 2, d1 = d0 + 1;

    int sub  = lane & 7;
    int quad = lane >> 3;
    float ad0 = g_adst2[d0];
    float ad1 = g_adst2[d1];

    int st0 = g_off[d0];
    int en0 = g_off[d1];
    int st1 = en0;
    int en1 = (d1 + 1 < NN) ? g_off[d1 + 1] : E;

    float acc0[8] = {}, acc1[8] = {};
    float ss0 = 0.f, ss1 = 0.f;

    if (quad == 0) {
        {
            float e0 = g_asrc2[d0] + ad0;
            float w0 = __expf(e0 > 0.f ? e0 : NEG * e0);
            ss0 = w0;
            uint4 raw = *(const uint4*)(g_xw2h + (size_t)d0 * F2 + sub * 8);
            float2 f0 = __half22float2(*(__half2*)&raw.x);
            float2 f1 = __half22float2(*(__half2*)&raw.y);
            float2 f2 = __half22float2(*(__half2*)&raw.z);
            float2 f3 = __half22float2(*(__half2*)&raw.w);
            acc0[0] = w0*f0.x; acc0[1] = w0*f0.y; acc0[2] = w0*f1.x; acc0[3] = w0*f1.y;
            acc0[4] = w0*f2.x; acc0[5] = w0*f2.y; acc0[6] = w0*f3.x; acc0[7] = w0*f3.y;
        }
        {
            float e0 = g_asrc2[d1] + ad1;
            float w0 = __expf(e0 > 0.f ? e0 : NEG * e0);
            ss1 = w0;
            uint4 raw = *(const uint4*)(g_xw2h + (size_t)d1 * F2 + sub * 8);
            float2 f0 = __half22float2(*(__half2*)&raw.x);
            float2 f1 = __half22float2(*(__half2*)&raw.y);
            float2 f2 = __half22float2(*(__half2*)&raw.z);
            float2 f3 = __half22float2(*(__half2*)&raw.w);
            acc1[0] = w0*f0.x; acc1[1] = w0*f0.y; acc1[2] = w0*f1.x; acc1[3] = w0*f1.y;
            acc1[4] = w0*f2.x; acc1[5] = w0*f2.y; acc1[6] = w0*f3.x; acc1[7] = w0*f3.y;
        }
    }

    int i0 = st0, i1 = st1;
    while (i0 < en0 || i1 < en1) {
        int c0 = (i0 < en0) ? min(en0 - i0, 32) : 0;
        int c1 = (i1 < en1) ? min(en1 - i1, 32) : 0;
        int sj0 = (lane < c0) ? g_csr[i0 + lane] : 0;
        int sj1 = (lane < c1) ? g_csr[i1 + lane] : 0;
        int cmax = max(c0, c1);
        for (int k = 0; k < cmax; k += 4) {
            int kk = k + quad;
            int selA = kk < c0 ? kk : 0;
            int selB = kk < c1 ? kk : 0;
            int sA = __shfl_sync(0xffffffffu, sj0, selA);
            int sB = __shfl_sync(0xffffffffu, sj1, selB);
            if (kk < c0) {
                float e = g_asrc2[sA] + ad0;
                float w = __expf(e > 0.f ? e : NEG * e);
                uint4 raw = *(const uint4*)(g_xw2h + (size_t)sA * F2 + sub * 8);
                float2 f0 = __half22float2(*(__half2*)&raw.x);
                float2 f1 = __half22float2(*(__half2*)&raw.y);
                float2 f2 = __half22float2(*(__half2*)&raw.z);
                float2 f3 = __half22float2(*(__half2*)&raw.w);
                ss0 += w;
                acc0[0] = fmaf(w, f0.x, acc0[0]); acc0[1] = fmaf(w, f0.y, acc0[1]);
                acc0[2] = fmaf(w, f1.x, acc0[2]); acc0[3] = fmaf(w, f1.y, acc0[3]);
                acc0[4] = fmaf(w, f2.x, acc0[4]); acc0[5] = fmaf(w, f2.y, acc0[5]);
                acc0[6] = fmaf(w, f3.x, acc0[6]); acc0[7] = fmaf(w, f3.y, acc0[7]);
            }
            if (kk < c1) {
                float e = g_asrc2[sB] + ad1;
                float w = __expf(e > 0.f ? e : NEG * e);
                uint4 raw = *(const uint4*)(g_xw2h + (size_t)sB * F2 + sub * 8);
                float2 f0 = __half22float2(*(__half2*)&raw.x);
                float2 f1 = __half22float2(*(__half2*)&raw.y);
                float2 f2 = __half22float2(*(__half2*)&raw.z);
                float2 f3 = __half22float2(*(__half2*)&raw.w);
                ss1 += w;
                acc1[0] = fmaf(w, f0.x, acc1[0]); acc1[1] = fmaf(w, f0.y, acc1[1]);
                acc1[2] = fmaf(w, f1.x, acc1[2]); acc1[3] = fmaf(w, f1.y, acc1[3]);
                acc1[4] = fmaf(w, f2.x, acc1[4]); acc1[5] = fmaf(w, f2.y, acc1[5]);
                acc1[6] = fmaf(w, f3.x, acc1[6]); acc1[7] = fmaf(w, f3.y, acc1[7]);
            }
        }
        i0 += 32; i1 += 32;
    }

    // combine the four quarter-warps per node
    ss0 += __shfl_xor_sync(0xffffffffu, ss0, 8);
    ss0 += __shfl_xor_sync(0xffffffffu, ss0, 16);
    ss1 += __shfl_xor_sync(0xffffffffu, ss1, 8);
    ss1 += __shfl_xor_sync(0xffffffffu, ss1, 16);
    #pragma unroll
    for (int j = 0; j < 8; j++) {
        acc0[j] += __shfl_xor_sync(0xffffffffu, acc0[j], 8);
        acc0[j] += __shfl_xor_sync(0xffffffffu, acc0[j], 16);
        acc1[j] += __shfl_xor_sync(0xffffffffu, acc1[j], 8);
        acc1[j] += __shfl_xor_sync(0xffffffffu, acc1[j], 16);
    }

    if (quad == 0) {
        int c0 = sub * 8;
        float inv0 = 1.f / (ss0 + EPSV);
        float inv1 = 1.f / (ss1 + EPSV);
        float o0[8], o1[8];
        #pragma unroll
        for (int j = 0; j < 8; j++) {
            float bb = b2[c0 + j];
            o0[j] = acc0[j] * inv0 + bb;
            o1[j] = acc1[j] * inv1 + bb;
        }
        float* p0 = out + (size_t)d0 * F2 + c0;
        float* p1 = out + (size_t)d1 * F2 + c0;
        *(float4*)(p0)     = make_float4(o0[0], o0[1], o0[2], o0[3]);
        *(float4*)(p0 + 4) = make_float4(o0[4], o0[5], o0[6], o0[7]);
        *(float4*)(p1)     = make_float4(o1[0], o1[1], o1[2], o1[3]);
        *(float4*)(p1 + 4) = make_float4(o1[4], o1[5], o1[6], o1[7]);
    }
}

// ---------------- launch ----------------------------------------------------
extern "C" void kernel_launch(void* const* d_in, const int* in_sizes, int n_in,
                              void* d_out, int out_size)
{
    const float* x        = (const float*)d_in[0];
    const int*   ei       = (const int*)  d_in[1];
    const float* W1       = (const float*)d_in[2];
    const float* att_src1 = (const float*)d_in[3];
    const float* att_dst1 = (const float*)d_in[4];
    const float* b1       = (const float*)d_in[5];
    const float* bn_gamma = (const float*)d_in[6];
    const float* bn_beta  = (const float*)d_in[7];
    const float* bn_mean  = (const float*)d_in[8];
    const float* bn_var   = (const float*)d_in[9];
    const float* W2       = (const float*)d_in[10];
    const float* att_src2 = (const float*)d_in[11];
    const float* att_dst2 = (const float*)d_in[12];
    const float* b2       = (const float*)d_in[13];
    float* out = (float*)d_out;

    int E  = in_sizes[1] / 2;
    const int* srcp = ei;
    const int* dstp = ei + E;

    __half *p_xw1h = nullptr, *p_xw2h = nullptr, *p_h1h = nullptr;
    cudaGetSymbolAddress((void**)&p_xw1h, g_xw1h);
    cudaGetSymbolAddress((void**)&p_h1h,  g_h1h);
    cudaGetSymbolAddress((void**)&p_xw2h, g_xw2h);

    static cudaStream_t s_side = nullptr;
    static cudaEvent_t ev_fork = nullptr, ev_join = nullptr;
    if (!s_side) {
        cudaStreamCreateWithFlags(&s_side, cudaStreamNonBlocking);
        cudaEventCreateWithFlags(&ev_fork, cudaEventDisableTiming);
        cudaEventCreateWithFlags(&ev_join, cudaEventDisableTiming);
    }

    bool vec_ok = (E % 4 == 0) &&
                  ((((uintptr_t)srcp) & 15u) == 0) &&
                  ((((uintptr_t)dstp) & 15u) == 0);

    // ---- fork: CSR build + W2 conversion on side stream; GEMM1 on main ------
    cudaEventRecord(ev_fork, 0);
    cudaStreamWaitEvent(s_side, ev_fork, 0);

    w2conv_kernel<<<(F1 * F2 + 255) / 256, 256, 0, s_side>>>(W2);
    if (vec_ok) {
        hist8_kernel<<<((E + 7) / 8 + 255) / 256, 256, 0, s_side>>>(dstp, E);
    } else {
        hist1_kernel<<<(E + 255) / 256, 256, 0, s_side>>>(dstp, E);
    }
    scanA_kernel<<<NBLK, 256, 0, s_side>>>();
    scanC_kernel<<<NBLK, 256, 0, s_side>>>();
    if (vec_ok) {
        scatter8_kernel<<<((E + 7) / 8 + 255) / 256, 256, 0, s_side>>>(srcp, dstp, E);
    } else {
        scatter1_kernel<<<(E + 255) / 256, 256, 0, s_side>>>(srcp, dstp, E);
    }

    {
        dim3 grid(1, (NN + 127) / 128);
        gemm1_kernel<<<grid, 256>>>(x, W1, p_xw1h, att_src1, att_dst1, NN);
    }

    // ---- join ----------------------------------------------------------------
    cudaEventRecord(ev_join, s_side);
    cudaStreamWaitEvent(0, ev_join, 0);

    // ---- layer 1 aggregate + layer 2 ------------------------------------------
    agg1_kernel<<<(NN / 2 * 32 + 255) / 256, 256>>>(b1, bn_gamma, bn_beta, bn_mean, bn_var, E);
    gemm2_wmma<<<(NN + 63) / 64, 128>>>(p_h1h, p_xw2h, att_src2, att_dst2, NN);
    agg2_kernel<<<(NN / 2 * 32 + 255) / 256, 256>>>(out, b2, E);
}

// round 17
// speedup vs baseline: 1.0284x; 1.0284x over previous
#include <cuda_runtime.h>
#include <cuda_fp16.h>
#include <mma.h>
#include <math.h>
#include <stdint.h>

using namespace nvcuda;

#define NN 50000
#define HH 4
#define CC 32
#define F1 128
#define F2 64
#define NEG 0.2f
#define EPSV 1e-16f
#define EMAX 1600000   // real edges only (self loops handled analytically)
#define NBLK ((NN + 255) / 256)
#define NPAD 50048     // NN rounded up to multiple of 64 (wmma tile safety)

// ---------------- scratch (device globals; no allocations allowed) ----------
__device__ __align__(16) __half g_xw1h[NN * F1];   // x@W1 half (agg1 gather)
__device__ __align__(16) __half g_h1h[NPAD * F1];  // layer1 output, half (gemm2 A)
__device__ float  g_asrc1[NN * HH];
__device__ float  g_adst1[NN * HH];
__device__ __align__(16) __half g_xw2h[NN * F2];   // h@W2 half (agg2 gather)
__device__ __align__(16) __half g_w2h[F1 * F2];    // W2 converted to half
__device__ float  g_asrc2[NN];
__device__ float  g_adst2[NN];
__device__ int    g_deg[NN];          // ZERO before each use; scanA re-zeroes
__device__ int    g_off[NN];          // CSR segment start
__device__ int    g_cur[NN];          // scatter cursor
__device__ int    g_bsum[256];        // block sums for scan
__device__ unsigned short g_csr[EMAX];  // src node per edge (NN < 65536)

// ---------------- GEMM1: xw1h = half(x @ W1), fused attn1 -------------------
__global__ __launch_bounds__(256) void gemm1_kernel(
    const float* __restrict__ A, const float* __restrict__ B,
    __half* __restrict__ Ch,
    const float* __restrict__ att_src, const float* __restrict__ att_dst, int M)
{
    const int BM = 128, BN = 128, BK = 8, KTOT = 128, NT = 256, TX = 16;
    __shared__ float As[2][BK * BM];
    __shared__ float Bs[2][BK * BN];

    int tid = threadIdx.x;
    int tx = tid % TX;
    int ty = tid / TX;
    int row0 = blockIdx.y * BM;

    float acc[8][8] = {};

    auto load_tile = [&](int buf, int kt) {
        int k0 = kt * BK;
        #pragma unroll
        for (int idx = tid; idx < BM * BK / 4; idx += NT) {
            int row = idx >> 1;
            int kc  = (idx & 1) * 4;
            int gr = row0 + row;
            float4 v = make_float4(0.f, 0.f, 0.f, 0.f);
            if (gr < M) v = *(const float4*)(A + (size_t)gr * KTOT + k0 + kc);
            As[buf][(kc + 0) * BM + row] = v.x;
            As[buf][(kc + 1) * BM + row] = v.y;
            As[buf][(kc + 2) * BM + row] = v.z;
            As[buf][(kc + 3) * BM + row] = v.w;
        }
        #pragma unroll
        for (int idx = tid; idx < BK * BN / 4; idx += NT) {
            int r  = idx / (BN / 4);
            int c4 = (idx % (BN / 4)) * 4;
            *(float4*)&Bs[buf][r * BN + c4] =
                *(const float4*)(B + (size_t)(k0 + r) * BN + c4);
        }
    };

    load_tile(0, 0);
    __syncthreads();

    int buf = 0;
    for (int kt = 0; kt < KTOT / BK; kt++) {
        if (kt + 1 < KTOT / BK) load_tile(buf ^ 1, kt + 1);
        #pragma unroll
        for (int kk = 0; kk < BK; kk++) {
            float4 a0 = *(const float4*)&As[buf][kk * BM + ty * 8];
            float4 a1 = *(const float4*)&As[buf][kk * BM + ty * 8 + 4];
            float4 b0 = *(const float4*)&Bs[buf][kk * BN + tx * 8];
            float4 b1 = *(const float4*)&Bs[buf][kk * BN + tx * 8 + 4];
            float av[8] = {a0.x,a0.y,a0.z,a0.w,a1.x,a1.y,a1.z,a1.w};
            float bv[8] = {b0.x,b0.y,b0.z,b0.w,b1.x,b1.y,b1.z,b1.w};
            #pragma unroll
            for (int i = 0; i < 8; i++)
                #pragma unroll
                for (int j = 0; j < 8; j++)
                    acc[i][j] = fmaf(av[i], bv[j], acc[i][j]);
        }
        __syncthreads();
        buf ^= 1;
    }

    float as1[8], ad1[8];
    #pragma unroll
    for (int j = 0; j < 8; j++) {
        as1[j] = att_src[tx * 8 + j];
        ad1[j] = att_dst[tx * 8 + j];
    }
    int h = tx >> 2;

    #pragma unroll
    for (int i = 0; i < 8; i++) {
        int gr = row0 + ty * 8 + i;
        float ps = 0.f, pd = 0.f;
        #pragma unroll
        for (int j = 0; j < 8; j++) {
            ps = fmaf(acc[i][j], as1[j], ps);
            pd = fmaf(acc[i][j], ad1[j], pd);
        }
        ps += __shfl_xor_sync(0xffffffffu, ps, 1);
        pd += __shfl_xor_sync(0xffffffffu, pd, 1);
        ps += __shfl_xor_sync(0xffffffffu, ps, 2);
        pd += __shfl_xor_sync(0xffffffffu, pd, 2);
        if (gr < M) {
            __half2 p0 = __floats2half2_rn(acc[i][0], acc[i][1]);
            __half2 p1 = __floats2half2_rn(acc[i][2], acc[i][3]);
            __half2 p2 = __floats2half2_rn(acc[i][4], acc[i][5]);
            __half2 p3 = __floats2half2_rn(acc[i][6], acc[i][7]);
            uint4 u = make_uint4(*(unsigned*)&p0, *(unsigned*)&p1,
                                 *(unsigned*)&p2, *(unsigned*)&p3);
            *(uint4*)(Ch + (size_t)gr * BN + tx * 8) = u;
            if ((tx & 3) == 0) {
                g_asrc1[gr * 4 + h] = ps;
                g_adst1[gr * 4 + h] = pd;
            }
        }
    }
}

// ---------------- W2 fp32 -> fp16 conversion --------------------------------
__global__ __launch_bounds__(256) void w2conv_kernel(const float* __restrict__ W2) {
    int i = blockIdx.x * blockDim.x + threadIdx.x;
    if (i < F1 * F2) g_w2h[i] = __float2half_rn(W2[i]);
}

// ---------------- GEMM2 (HMMA): xw2h = half(h1h @ W2h), fused attn2 ---------
__global__ __launch_bounds__(128) void gemm2_wmma(
    const __half* __restrict__ A,      // g_h1h [NPAD,128]
    __half* __restrict__ Ch,           // g_xw2h [NN,64]
    const float* __restrict__ att_src, const float* __restrict__ att_dst, int M)
{
    __shared__ float sm[64 * 64];
    int tid  = threadIdx.x;
    int warp = tid >> 5;
    int blk0 = blockIdx.x * 64;
    int row0 = blk0 + warp * 16;

    wmma::fragment<wmma::accumulator, 16, 16, 16, float> acc[4];
    #pragma unroll
    for (int n = 0; n < 4; n++) wmma::fill_fragment(acc[n], 0.f);

    wmma::fragment<wmma::matrix_a, 16, 16, 16, __half, wmma::row_major> afrag;
    wmma::fragment<wmma::matrix_b, 16, 16, 16, __half, wmma::row_major> bfrag;

    #pragma unroll
    for (int k0 = 0; k0 < F1; k0 += 16) {
        wmma::load_matrix_sync(afrag, A + (size_t)row0 * F1 + k0, F1);
        #pragma unroll
        for (int n = 0; n < 4; n++) {
            wmma::load_matrix_sync(bfrag, g_w2h + (size_t)k0 * F2 + n * 16, F2);
            wmma::mma_sync(acc[n], afrag, bfrag, acc[n]);
        }
    }

    #pragma unroll
    for (int n = 0; n < 4; n++)
        wmma::store_matrix_sync(&sm[warp * 16 * 64 + n * 16], acc[n], 64,
                                wmma::mem_row_major);
    __syncthreads();

    int r    = tid >> 1;
    int halfi = tid & 1;
    int gr = blk0 + r;
    const float* rowp = &sm[r * 64 + halfi * 32];
    const float* asp = att_src + halfi * 32;
    const float* adp = att_dst + halfi * 32;

    float ps = 0.f, pd = 0.f;
    float v[32];
    #pragma unroll
    for (int j = 0; j < 32; j++) {
        v[j] = rowp[j];
        ps = fmaf(v[j], asp[j], ps);
        pd = fmaf(v[j], adp[j], pd);
    }
    ps += __shfl_xor_sync(0xffffffffu, ps, 1);
    pd += __shfl_xor_sync(0xffffffffu, pd, 1);

    if (gr < M) {
        #pragma unroll
        for (int c = 0; c < 4; c++) {
            __half2 p0 = __floats2half2_rn(v[c*8+0], v[c*8+1]);
            __half2 p1 = __floats2half2_rn(v[c*8+2], v[c*8+3]);
            __half2 p2 = __floats2half2_rn(v[c*8+4], v[c*8+5]);
            __half2 p3 = __floats2half2_rn(v[c*8+6], v[c*8+7]);
            uint4 u = make_uint4(*(unsigned*)&p0, *(unsigned*)&p1,
                                 *(unsigned*)&p2, *(unsigned*)&p3);
            *(uint4*)(Ch + (size_t)gr * F2 + halfi * 32 + c * 8) = u;
        }
        if (halfi == 0) {
            g_asrc2[gr] = ps;
            g_adst2[gr] = pd;
        }
    }
}

// ---------------- CSR build (real edges only) -------------------------------
__global__ __launch_bounds__(256) void hist8_kernel(const int* __restrict__ dstp, int E) {
    int i = blockIdx.x * blockDim.x + threadIdx.x;
    int e8 = i * 8;
    if (e8 + 7 < E) {
        int4 a = *(const int4*)(dstp + e8);
        int4 b = *(const int4*)(dstp + e8 + 4);
        atomicAdd(&g_deg[a.x], 1); atomicAdd(&g_deg[a.y], 1);
        atomicAdd(&g_deg[a.z], 1); atomicAdd(&g_deg[a.w], 1);
        atomicAdd(&g_deg[b.x], 1); atomicAdd(&g_deg[b.y], 1);
        atomicAdd(&g_deg[b.z], 1); atomicAdd(&g_deg[b.w], 1);
    } else {
        for (int e = e8; e < E; e++) atomicAdd(&g_deg[dstp[e]], 1);
    }
}

__global__ __launch_bounds__(256) void hist1_kernel(const int* __restrict__ dstp, int E) {
    int e = blockIdx.x * blockDim.x + threadIdx.x;
    if (e < E) atomicAdd(&g_deg[dstp[e]], 1);
}

__global__ __launch_bounds__(256) void scanA_kernel() {
    __shared__ int wsum[8];
    int t = threadIdx.x, lane = t & 31, w = t >> 5;
    int idx = blockIdx.x * 256 + t;
    int v = (idx < NN) ? g_deg[idx] : 0;
    int x = v;
    #pragma unroll
    for (int o = 1; o < 32; o <<= 1) {
        int tt = __shfl_up_sync(0xffffffffu, x, o);
        if (lane >= o) x += tt;
    }
    if (lane == 31) wsum[w] = x;
    __syncthreads();
    if (w == 0) {
        int s = (lane < 8) ? wsum[lane] : 0;
        #pragma unroll
        for (int o = 1; o < 8; o <<= 1) {
            int tt = __shfl_up_sync(0xffffffffu, s, o);
            if (lane >= o) s += tt;
        }
        if (lane < 8) wsum[lane] = s;
    }
    __syncthreads();
    int pre = (w > 0 ? wsum[w - 1] : 0) + (x - v);
    if (idx < NN) {
        g_off[idx] = pre;
        g_deg[idx] = 0;               // self-clean for next invocation
    }
    if (t == 255) g_bsum[blockIdx.x] = pre + v;
}

__global__ __launch_bounds__(256) void scanC_kernel() {
    __shared__ int wsum[8];
    __shared__ int s_total;
    int t = threadIdx.x, lane = t & 31, w = t >> 5;
    int v = (t < (int)blockIdx.x && t < NBLK) ? g_bsum[t] : 0;
    #pragma unroll
    for (int o = 16; o > 0; o >>= 1) v += __shfl_xor_sync(0xffffffffu, v, o);
    if (lane == 0) wsum[w] = v;
    __syncthreads();
    if (t == 0) {
        int s = 0;
        #pragma unroll
        for (int k = 0; k < 8; k++) s += wsum[k];
        s_total = s;
    }
    __syncthreads();
    int idx = blockIdx.x * 256 + t;
    if (idx < NN) {
        int o = g_off[idx] + s_total;
        g_off[idx] = o;
        g_cur[idx] = o;
    }
}

__global__ __launch_bounds__(256) void scatter8_kernel(
    const int* __restrict__ srcp, const int* __restrict__ dstp, int E)
{
    int i = blockIdx.x * blockDim.x + threadIdx.x;
    int e8 = i * 8;
    if (e8 + 7 < E) {
        int4 sa = *(const int4*)(srcp + e8);
        int4 sb = *(const int4*)(srcp + e8 + 4);
        int4 da = *(const int4*)(dstp + e8);
        int4 db = *(const int4*)(dstp + e8 + 4);
        g_csr[atomicAdd(&g_cur[da.x], 1)] = (unsigned short)sa.x;
        g_csr[atomicAdd(&g_cur[da.y], 1)] = (unsigned short)sa.y;
        g_csr[atomicAdd(&g_cur[da.z], 1)] = (unsigned short)sa.z;
        g_csr[atomicAdd(&g_cur[da.w], 1)] = (unsigned short)sa.w;
        g_csr[atomicAdd(&g_cur[db.x], 1)] = (unsigned short)sb.x;
        g_csr[atomicAdd(&g_cur[db.y], 1)] = (unsigned short)sb.y;
        g_csr[atomicAdd(&g_cur[db.z], 1)] = (unsigned short)sb.z;
        g_csr[atomicAdd(&g_cur[db.w], 1)] = (unsigned short)sb.w;
    } else {
        for (int e = e8; e < E; e++)
            g_csr[atomicAdd(&g_cur[dstp[e]], 1)] = (unsigned short)srcp[e];
    }
}

__global__ __launch_bounds__(256) void scatter1_kernel(
    const int* __restrict__ srcp, const int* __restrict__ dstp, int E)
{
    int e = blockIdx.x * blockDim.x + threadIdx.x;
    if (e < E) g_csr[atomicAdd(&g_cur[dstp[e]], 1)] = (unsigned short)srcp[e];
}

// ---------------- layer 1 fused gather + self-loop + bias + BN + ELU --------
// R11/R14 geometry: lane covers 8 cols; half-warps process alternating edges.
__global__ __launch_bounds__(256) void agg1_kernel(
    const float* __restrict__ b1,
    const float* __restrict__ gamma, const float* __restrict__ beta,
    const float* __restrict__ mean,  const float* __restrict__ var, int E)
{
    int d = (blockIdx.x * blockDim.x + threadIdx.x) >> 5;
    int lane = threadIdx.x & 31;
    if (d >= NN) return;

    int sub  = lane & 15;
    int half = lane >> 4;
    int h = sub >> 2;
    float ad = g_adst1[d * 4 + h];

    int start = g_off[d];
    int end   = (d + 1 < NN) ? g_off[d + 1] : E;

    float acc[8] = {};
    float ssum = 0.f;

    if (half == 0) {
        float e0 = g_asrc1[d * 4 + h] + ad;
        float w0 = __expf(e0 > 0.f ? e0 : NEG * e0);
        ssum = w0;
        uint4 raw = *(const uint4*)(g_xw1h + (size_t)d * F1 + sub * 8);
        float2 f0 = __half22float2(*(__half2*)&raw.x);
        float2 f1 = __half22float2(*(__half2*)&raw.y);
        float2 f2 = __half22float2(*(__half2*)&raw.z);
        float2 f3 = __half22float2(*(__half2*)&raw.w);
        acc[0] = w0 * f0.x; acc[1] = w0 * f0.y;
        acc[2] = w0 * f1.x; acc[3] = w0 * f1.y;
        acc[4] = w0 * f2.x; acc[5] = w0 * f2.y;
        acc[6] = w0 * f3.x; acc[7] = w0 * f3.y;
    }

    for (int i = start; i < end; i += 32) {
        int cnt = min(end - i, 32);
        int sj = (lane < cnt) ? (int)g_csr[i + lane] : 0;
        #pragma unroll 8
        for (int k = 0; k < cnt; k += 2) {
            int kk = k + half;
            int sel = kk < cnt ? kk : 0;
            int s = __shfl_sync(0xffffffffu, sj, sel);
            if (kk < cnt) {
                float e = g_asrc1[s * 4 + h] + ad;
                float w = __expf(e > 0.f ? e : NEG * e);
                uint4 raw = *(const uint4*)(g_xw1h + (size_t)s * F1 + sub * 8);
                float2 f0 = __half22float2(*(__half2*)&raw.x);
                float2 f1 = __half22float2(*(__half2*)&raw.y);
                float2 f2 = __half22float2(*(__half2*)&raw.z);
                float2 f3 = __half22float2(*(__half2*)&raw.w);
                ssum += w;
                acc[0] = fmaf(w, f0.x, acc[0]); acc[1] = fmaf(w, f0.y, acc[1]);
                acc[2] = fmaf(w, f1.x, acc[2]); acc[3] = fmaf(w, f1.y, acc[3]);
                acc[4] = fmaf(w, f2.x, acc[4]); acc[5] = fmaf(w, f2.y, acc[5]);
                acc[6] = fmaf(w, f3.x, acc[6]); acc[7] = fmaf(w, f3.y, acc[7]);
            }
        }
    }

    ssum += __shfl_xor_sync(0xffffffffu, ssum, 16);
    #pragma unroll
    for (int j = 0; j < 8; j++)
        acc[j] += __shfl_xor_sync(0xffffffffu, acc[j], 16);

    if (half == 0) {
        float inv = 1.f / (ssum + EPSV);
        int c0 = sub * 8;
        float o[8];
        #pragma unroll
        for (int j = 0; j < 8; j++) {
            int c = c0 + j;
            float hv = acc[j] * inv + b1[c];
            hv = (hv - mean[c]) * rsqrtf(var[c] + 1e-5f) * gamma[c] + beta[c];
            o[j] = hv > 0.f ? hv : expm1f(hv);
        }
        __half2 p0 = __floats2half2_rn(o[0], o[1]);
        __half2 p1 = __floats2half2_rn(o[2], o[3]);
        __half2 p2 = __floats2half2_rn(o[4], o[5]);
        __half2 p3 = __floats2half2_rn(o[6], o[7]);
        uint4 u = make_uint4(*(unsigned*)&p0, *(unsigned*)&p1,
                             *(unsigned*)&p2, *(unsigned*)&p3);
        *(uint4*)(g_h1h + (size_t)d * F1 + c0) = u;
    }
}

// ---------------- layer 2 fused gather + self-loop + bias -> out ------------
// R11/R14 geometry: lane covers 8 cols; quarter-warps process 4 edges/step.
__global__ __launch_bounds__(256) void agg2_kernel(
    float* __restrict__ out, const float* __restrict__ b2, int E)
{
    int d = (blockIdx.x * blockDim.x + threadIdx.x) >> 5;
    int lane = threadIdx.x & 31;
    if (d >= NN) return;

    int sub  = lane & 7;
    int quad = lane >> 3;
    float ad = g_adst2[d];

    int start = g_off[d];
    int end   = (d + 1 < NN) ? g_off[d + 1] : E;

    float acc[8] = {};
    float ssum = 0.f;

    if (quad == 0) {
        float e0 = g_asrc2[d] + ad;
        float w0 = __expf(e0 > 0.f ? e0 : NEG * e0);
        ssum = w0;
        uint4 raw = *(const uint4*)(g_xw2h + (size_t)d * F2 + sub * 8);
        float2 f0 = __half22float2(*(__half2*)&raw.x);
        float2 f1 = __half22float2(*(__half2*)&raw.y);
        float2 f2 = __half22float2(*(__half2*)&raw.z);
        float2 f3 = __half22float2(*(__half2*)&raw.w);
        acc[0] = w0 * f0.x; acc[1] = w0 * f0.y;
        acc[2] = w0 * f1.x; acc[3] = w0 * f1.y;
        acc[4] = w0 * f2.x; acc[5] = w0 * f2.y;
        acc[6] = w0 * f3.x; acc[7] = w0 * f3.y;
    }

    for (int i = start; i < end; i += 32) {
        int cnt = min(end - i, 32);
        int sj = (lane < cnt) ? (int)g_csr[i + lane] : 0;
        #pragma unroll 4
        for (int k = 0; k < cnt; k += 4) {
            int kk = k + quad;
            int sel = kk < cnt ? kk : 0;
            int s = __shfl_sync(0xffffffffu, sj, sel);
            if (kk < cnt) {
                float e = g_asrc2[s] + ad;
                float w = __expf(e > 0.f ? e : NEG * e);
                uint4 raw = *(const uint4*)(g_xw2h + (size_t)s * F2 + sub * 8);
                float2 f0 = __half22float2(*(__half2*)&raw.x);
                float2 f1 = __half22float2(*(__half2*)&raw.y);
                float2 f2 = __half22float2(*(__half2*)&raw.z);
                float2 f3 = __half22float2(*(__half2*)&raw.w);
                ssum += w;
                acc[0] = fmaf(w, f0.x, acc[0]); acc[1] = fmaf(w, f0.y, acc[1]);
                acc[2] = fmaf(w, f1.x, acc[2]); acc[3] = fmaf(w, f1.y, acc[3]);
                acc[4] = fmaf(w, f2.x, acc[4]); acc[5] = fmaf(w, f2.y, acc[5]);
                acc[6] = fmaf(w, f3.x, acc[6]); acc[7] = fmaf(w, f3.y, acc[7]);
            }
        }
    }

    ssum += __shfl_xor_sync(0xffffffffu, ssum, 8);
    ssum += __shfl_xor_sync(0xffffffffu, ssum, 16);
    #pragma unroll
    for (int j = 0; j < 8; j++) {
        acc[j] += __shfl_xor_sync(0xffffffffu, acc[j], 8);
        acc[j] += __shfl_xor_sync(0xffffffffu, acc[j], 16);
    }

    if (quad == 0) {
        float inv = 1.f / (ssum + EPSV);
        int c0 = sub * 8;
        float o[8];
        #pragma unroll
        for (int j = 0; j < 8; j++)
            o[j] = acc[j] * inv + b2[c0 + j];
        float* outp = out + (size_t)d * F2 + c0;
        *(float4*)(outp)     = make_float4(o[0], o[1], o[2], o[3]);
        *(float4*)(outp + 4) = make_float4(o[4], o[5], o[6], o[7]);
    }
}

// ---------------- launch ----------------------------------------------------
extern "C" void kernel_launch(void* const* d_in, const int* in_sizes, int n_in,
                              void* d_out, int out_size)
{
    const float* x        = (const float*)d_in[0];
    const int*   ei       = (const int*)  d_in[1];
    const float* W1       = (const float*)d_in[2];
    const float* att_src1 = (const float*)d_in[3];
    const float* att_dst1 = (const float*)d_in[4];
    const float* b1       = (const float*)d_in[5];
    const float* bn_gamma = (const float*)d_in[6];
    const float* bn_beta  = (const float*)d_in[7];
    const float* bn_mean  = (const float*)d_in[8];
    const float* bn_var   = (const float*)d_in[9];
    const float* W2       = (const float*)d_in[10];
    const float* att_src2 = (const float*)d_in[11];
    const float* att_dst2 = (const float*)d_in[12];
    const float* b2       = (const float*)d_in[13];
    float* out = (float*)d_out;

    int E  = in_sizes[1] / 2;
    const int* srcp = ei;
    const int* dstp = ei + E;

    __half *p_xw1h = nullptr, *p_xw2h = nullptr, *p_h1h = nullptr;
    cudaGetSymbolAddress((void**)&p_xw1h, g_xw1h);
    cudaGetSymbolAddress((void**)&p_h1h,  g_h1h);
    cudaGetSymbolAddress((void**)&p_xw2h, g_xw2h);

    static cudaStream_t s_side = nullptr;
    static cudaEvent_t ev_fork = nullptr, ev_join = nullptr;
    if (!s_side) {
        cudaStreamCreateWithFlags(&s_side, cudaStreamNonBlocking);
        cudaEventCreateWithFlags(&ev_fork, cudaEventDisableTiming);
        cudaEventCreateWithFlags(&ev_join, cudaEventDisableTiming);
    }

    bool vec_ok = (E % 4 == 0) &&
                  ((((uintptr_t)srcp) & 15u) == 0) &&
                  ((((uintptr_t)dstp) & 15u) == 0);

    // ---- fork: CSR build + W2 conversion on side stream; GEMM1 on main ------
    cudaEventRecord(ev_fork, 0);
    cudaStreamWaitEvent(s_side, ev_fork, 0);

    w2conv_kernel<<<(F1 * F2 + 255) / 256, 256, 0, s_side>>>(W2);
    if (vec_ok) {
        hist8_kernel<<<((E + 7) / 8 + 255) / 256, 256, 0, s_side>>>(dstp, E);
    } else {
        hist1_kernel<<<(E + 255) / 256, 256, 0, s_side>>>(dstp, E);
    }
    scanA_kernel<<<NBLK, 256, 0, s_side>>>();
    scanC_kernel<<<NBLK, 256, 0, s_side>>>();
    if (vec_ok) {
        scatter8_kernel<<<((E + 7) / 8 + 255) / 256, 256, 0, s_side>>>(srcp, dstp, E);
    } else {
        scatter1_kernel<<<(E + 255) / 256, 256, 0, s_side>>>(srcp, dstp, E);
    }

    {
        dim3 grid(1, (NN + 127) / 128);
        gemm1_kernel<<<grid, 256>>>(x, W1, p_xw1h, att_src1, att_dst1, NN);
    }

    // ---- join ----------------------------------------------------------------
    cudaEventRecord(ev_join, s_side);
    cudaStreamWaitEvent(0, ev_join, 0);

    // ---- layer 1 aggregate + layer 2 ------------------------------------------
    agg1_kernel<<<(NN * 32 + 255) / 256, 256>>>(b1, bn_gamma, bn_beta, bn_mean, bn_var, E);
    gemm2_wmma<<<(NN + 63) / 64, 128>>>(p_h1h, p_xw2h, att_src2, att_dst2, NN);
    agg2_kernel<<<(NN * 32 + 255) / 256, 256>>>(out, b2, E);
}